// round 11
// baseline (speedup 1.0000x reference)
#include <cuda_runtime.h>

#define NPRIMES 168
#define TPB 512            // 384 producer threads (12 warps) + 128 consumers (4 warps)
#define PT  384
#define COLS 128           // columns per tile
#define TILES 4            // tiles per block (block owns 512 columns)
#define SUBS  16           // 16 sub-tiles of 32 columns (1 warp gathers 1 sub-tile)
#define PW    12           // producer warps
#define TABN (NPRIMES * 1000)

// Interleaved (kernel, bias) table: one LDG.64 fetches both values.
__device__ float2 g_tab[TABN];

// Per-prime magic-mod descriptor (compile-time, constant memory):
//  magic = floor(2^32/p)+1  ->  k % p == k - p*umulhi(k, magic)   (k < 2^20)
struct PInfo { unsigned magic; int p; };

#define PRIME_LIST \
 X(2) X(3) X(5) X(7) X(11) X(13) X(17) X(19) X(23) X(29) \
 X(31) X(37) X(41) X(43) X(47) X(53) X(59) X(61) X(67) X(71) \
 X(73) X(79) X(83) X(89) X(97) X(101) X(103) X(107) X(109) X(113) \
 X(127) X(131) X(137) X(139) X(149) X(151) X(157) X(163) X(167) X(173) \
 X(179) X(181) X(191) X(193) X(197) X(199) X(211) X(223) X(227) X(229) \
 X(233) X(239) X(241) X(251) X(257) X(263) X(269) X(271) X(277) X(281) \
 X(283) X(293) X(307) X(311) X(313) X(317) X(331) X(337) X(347) X(349) \
 X(353) X(359) X(367) X(373) X(379) X(383) X(389) X(397) X(401) X(409) \
 X(419) X(421) X(431) X(433) X(439) X(443) X(449) X(457) X(461) X(463) \
 X(467) X(479) X(487) X(491) X(499) X(503) X(509) X(521) X(523) X(541) \
 X(547) X(557) X(563) X(569) X(571) X(577) X(587) X(593) X(599) X(601) \
 X(607) X(613) X(617) X(619) X(631) X(641) X(643) X(647) X(653) X(659) \
 X(661) X(673) X(677) X(683) X(691) X(701) X(709) X(719) X(727) X(733) \
 X(739) X(743) X(751) X(757) X(761) X(769) X(773) X(787) X(797) X(809) \
 X(811) X(821) X(823) X(827) X(829) X(839) X(853) X(857) X(859) X(863) \
 X(877) X(881) X(883) X(887) X(907) X(911) X(919) X(929) X(937) X(941) \
 X(947) X(953) X(967) X(971) X(977) X(983) X(991) X(997)

__constant__ PInfo C_PI[NPRIMES] = {
#define X(p) { 0xFFFFFFFFu / (unsigned)(p) + 1u, (p) },
  PRIME_LIST
#undef X
};

__global__ __launch_bounds__(256)
void interleave_tab(const float* __restrict__ kern, const float* __restrict__ bias)
{
    int i = blockIdx.x * 256 + threadIdx.x;
    if (i < TABN) g_tab[i] = make_float2(kern[i], bias[i]);
}

__global__ __launch_bounds__(TPB, 3)
void bwl_prime_main(const float* __restrict__ x,
                    float* __restrict__ out,
                    int N, int B)
{
    __shared__ float2 wb_s[TILES][COLS];   // (w,b) per column
    __shared__ int    cnt[TILES];          // sub-tiles completed per tile

    const int t    = threadIdx.x;
    const int base = blockIdx.x * (COLS * TILES);
    const size_t nv = (size_t)(N >> 2);

    if (t < TILES) cnt[t] = 0;
    __syncthreads();                        // only sync before role divergence

    if (t < PT) {
        // ============ PRODUCERS: 12 warps ============
        const int w    = t >> 5;
        const int lane = t & 31;

        // Each warp independently gathers 32-column sub-tiles (no ramp:
        // first tiles complete after ~1/4 of this block's gather work).
        for (int sub = w; sub < SUBS; sub += PW) {
            const int tile = sub >> 2;
            const int part = sub & 3;
            const unsigned k = (unsigned)(base + tile * COLS + part * 32 + lane);

            float wv = 0.f, av = 0.f;
            const float2* __restrict__ row = g_tab;
#pragma unroll 8
            for (int i = 0; i < NPRIMES; ++i) {
                const PInfo pi = C_PI[i];
                int m = (int)(k - (unsigned)pi.p * __umulhi(k, pi.magic)); // k%p
                float2 e = __ldg(row + m);
                wv += e.x; av += e.y;
                row += 1000;
            }
            wb_s[tile][part * 32 + lane] = make_float2(wv, av);

            __syncwarp();
            if (lane == 0) {
                __threadfence_block();                 // release wb stores
                atomicAdd_block(&cnt[tile], 1);
            }
        }

        // all producers done gathering -> every flag is set
        asm volatile("bar.sync 1, %0;" :: "n"(PT) : "memory");

        // ---- role switch: producers stream rows [B/2, B) ----
        const int col4 = t & 31;
        const int g    = t >> 5;            // 0..11
        for (int s = 0; s < TILES; ++s) {
            const float2 q0 = wb_s[s][col4 * 4 + 0];
            const float2 q1 = wb_s[s][col4 * 4 + 1];
            const float2 q2 = wb_s[s][col4 * 4 + 2];
            const float2 q3 = wb_s[s][col4 * 4 + 3];
            const int k0 = base + s * COLS;

            for (int r = (B >> 1) + g; r < B; r += PW) {
                const float4* xp = reinterpret_cast<const float4*>(x)
                                   + (size_t)r * nv + (k0 >> 2) + col4;
                float4*       op = reinterpret_cast<float4*>(out)
                                   + (size_t)r * nv + (k0 >> 2) + col4;
                float4 xi = __ldcs(xp);
                float4 o;
                o.x = fmaf(xi.x, q0.x, q0.y);
                o.y = fmaf(xi.y, q1.x, q1.y);
                o.z = fmaf(xi.z, q2.x, q2.y);
                o.w = fmaf(xi.w, q3.x, q3.y);
                __stcs(op, o);
            }
        }
    } else {
        // ============ CONSUMERS: 4 warps, stream rows [0, B/2) ============
        const int ct   = t - PT;
        const int col4 = ct & 31;
        const int rpg  = B >> 3;            // 8 rows per group
        const int rbeg = (ct >> 5) * rpg;   // group 0..3 -> rows 0..31

        for (int s = 0; s < TILES; ++s) {
            // acquire-spin until all 4 sub-tiles of tile s are published
            {
                unsigned ca = (unsigned)__cvta_generic_to_shared(&cnt[s]);
                int f;
                for (;;) {
                    asm volatile("ld.acquire.cta.shared.b32 %0, [%1];"
                                 : "=r"(f) : "r"(ca) : "memory");
                    if (f == 4) break;
                    __nanosleep(32);
                }
            }
            __threadfence_block();

            const float2 q0 = wb_s[s][col4 * 4 + 0];
            const float2 q1 = wb_s[s][col4 * 4 + 1];
            const float2 q2 = wb_s[s][col4 * 4 + 2];
            const float2 q3 = wb_s[s][col4 * 4 + 3];

            const int k0 = base + s * COLS;
            const float4* __restrict__ xv = reinterpret_cast<const float4*>(x)
                                            + (size_t)rbeg * nv + (k0 >> 2) + col4;
            float4* __restrict__       ov = reinterpret_cast<float4*>(out)
                                            + (size_t)rbeg * nv + (k0 >> 2) + col4;

#pragma unroll 8
            for (int r = 0; r < rpg; ++r) {
                float4 xi = __ldcs(xv);
                float4 o;
                o.x = fmaf(xi.x, q0.x, q0.y);
                o.y = fmaf(xi.y, q1.x, q1.y);
                o.z = fmaf(xi.z, q2.x, q2.y);
                o.w = fmaf(xi.w, q3.x, q3.y);
                __stcs(ov, o);
                xv += nv;
                ov += nv;
            }
        }
    }
}

extern "C" void kernel_launch(void* const* d_in, const int* in_sizes, int n_in,
                              void* d_out, int out_size)
{
    const float* x  = (const float*)d_in[0];   // (B, N) float32
    const float* kr = (const float*)d_in[1];   // (168, 1000) float32
    const float* br = (const float*)d_in[2];   // (168, 1000) float32
    float* out = (float*)d_out;

    const int N = 524288;
    const int B = in_sizes[0] / N;             // 64

    interleave_tab<<<(TABN + 255) / 256, 256>>>(kr, br);

    const int grid = N / (COLS * TILES);       // 1024 blocks
    bwl_prime_main<<<grid, TPB>>>(x, out, N, B);
}